// round 15
// baseline (speedup 1.0000x reference)
#include <cuda_runtime.h>
#include <cuda_bf16.h>
#include <mma.h>
#include <math.h>
#include <cstdint>

using namespace nvcuda;

// ---------------- problem constants ----------------
#define NL 2          // layers
#define NB 4          // batch
#define NT 64         // time
#define ND 512        // input dim
#define NH 512        // hidden/proj dim
#define NC 4096       // cell dim
#define NG (4*NC)     // 16384 gate rows per dir
#define CLIPV 3.0f
#define NPART 8       // proj-partial partitions (64 blocks add per partition)
#define WI_ELEMS ((size_t)2 * NG * ND)      // 16,777,216 per layer
#define A_ELEMS  ((size_t)2 * NB * NT * NH) // 262,144 (both dirs)
// pi dynamic smem: As[2buf][2hl][128][40] + Bs[2buf][2hl][64][40], bf16
#define PI_SMEM_ELEMS (2*2*128*40 + 2*2*64*40)
#define PI_SMEM_BYTES (PI_SMEM_ELEMS * 2)   // 61440

// ---------------- device scratch (static allocation: allowed) ----------------
__device__ __align__(16) float g_pi[(size_t)2 * NB * NT * NG];   // 32 MiB
__device__ __align__(16) float g_x [(size_t)2 * NB * NT * NH];
__device__ __align__(16) float g_y [(size_t)2 * NB * NT * NH];
__device__ __align__(16) float g_c [(size_t)2 * NB * NC];
__device__ __align__(16) float g_h [(size_t)2 * NB * NH];
__device__ __align__(16) __nv_bfloat16 g_wih[WI_ELEMS];
__device__ __align__(16) __nv_bfloat16 g_wil[WI_ELEMS];
__device__ __align__(16) __nv_bfloat16 g_ah[A_ELEMS];
__device__ __align__(16) __nv_bfloat16 g_al[A_ELEMS];
__device__ __align__(16) float g_wpT[(size_t)2 * NC * NH];       // 16.8 MB
// proj partial accumulators (single buffer; last-block finalizer re-zeros)
__device__ __align__(16) float g_hpp[NPART][2 * NB * NH];
__device__ int g_fcnt[2];   // per-dir arrival counters; zero-init, self-reset

__device__ __forceinline__ void pdl_sync() {
#if defined(__CUDA_ARCH__) && (__CUDA_ARCH__ >= 900)
    cudaGridDependencySynchronize();
#endif
}

__device__ __forceinline__ float dot4(float4 a, float4 b) {
    return a.x*b.x + a.y*b.y + a.z*b.z + a.w*b.w;
}
__device__ __forceinline__ float sigmoidf_(float x) { return 1.0f / (1.0f + expf(-x)); }
__device__ __forceinline__ float clip3(float x)     { return fminf(CLIPV, fmaxf(-CLIPV, x)); }

__device__ __forceinline__ void cpa16(uint32_t dst, const void* src) {
    asm volatile("cp.async.cg.shared.global [%0], [%1], 16;" :: "r"(dst), "l"(src));
}
__device__ __forceinline__ void cpa_commit() {
    asm volatile("cp.async.commit_group;");
}

// ---------------- init: zero h and c (reference resets per layer/direction) ----
__global__ void init_state_kernel() {
    pdl_sync();
    int idx = blockIdx.x * blockDim.x + threadIdx.x;
    if (idx < 2 * NB * NC) g_c[idx] = 0.0f;
    if (idx < 2 * NB * NH) g_h[idx] = 0.0f;
}

// ---------------- conversion: Wi fp32 -> split-bf16 hi/lo ----------------------
__global__ void __launch_bounds__(256)
convert_wi_kernel(const float* __restrict__ Wi_l)
{
    pdl_sync();
    size_t idx = ((size_t)blockIdx.x * 256 + threadIdx.x) * 8;
    if (idx >= WI_ELEMS) return;
    float4 a = __ldcs((const float4*)(Wi_l + idx));
    float4 b = __ldcs((const float4*)(Wi_l + idx + 4));
    float v[8] = {a.x, a.y, a.z, a.w, b.x, b.y, b.z, b.w};
    __align__(16) __nv_bfloat16 hi[8], lo[8];
#pragma unroll
    for (int q = 0; q < 8; q++) {
        hi[q] = __float2bfloat16(v[q]);
        lo[q] = __float2bfloat16(v[q] - __bfloat162float(hi[q]));
    }
    *(uint4*)(g_wih + idx) = *(const uint4*)hi;
    *(uint4*)(g_wil + idx) = *(const uint4*)lo;
}

// ---------------- conversion: A (inputs or g_x) -> split-bf16 hi/lo ------------
__global__ void __launch_bounds__(256)
convert_a_kernel(const float* __restrict__ x0, int l)
{
    pdl_sync();
    size_t idx = ((size_t)blockIdx.x * 256 + threadIdx.x) * 8;
    if (idx >= A_ELEMS) return;
    const size_t d   = idx >> 17;
    const size_t off = idx & 131071;
    const float* src = l ? (g_x + (d << 17) + off) : (x0 + off);
    float4 a = *(const float4*)src;
    float4 b = *(const float4*)(src + 4);
    float v[8] = {a.x, a.y, a.z, a.w, b.x, b.y, b.z, b.w};
    __align__(16) __nv_bfloat16 hi[8], lo[8];
#pragma unroll
    for (int q = 0; q < 8; q++) {
        hi[q] = __float2bfloat16(v[q]);
        lo[q] = __float2bfloat16(v[q] - __bfloat162float(hi[q]));
    }
    *(uint4*)(g_ah + idx) = *(const uint4*)hi;
    *(uint4*)(g_al + idx) = *(const uint4*)lo;
}

// ---------------- transpose Wp: (2,512,4096) -> g_wpT (2,4096,512) -------------
__global__ void __launch_bounds__(256)
transpose_wp_kernel(const float* __restrict__ Wp_l)
{
    pdl_sync();
    __shared__ float tile[32][33];
    const int d = blockIdx.z;
    const int jb = blockIdx.x * 32;
    const int ib = blockIdx.y * 32;
    const int tx = threadIdx.x & 31, ty = threadIdx.x >> 5;
    const float* src = Wp_l + (size_t)d * NH * NC;
#pragma unroll
    for (int r = 0; r < 4; r++) {
        int i = ib + ty + r * 8;
        tile[ty + r * 8][tx] = src[(size_t)i * NC + jb + tx];
    }
    __syncthreads();
    float* dst = g_wpT + (size_t)d * NC * NH;
#pragma unroll
    for (int r = 0; r < 4; r++) {
        int j = jb + ty + r * 8;
        dst[(size_t)j * NH + ib + tx] = tile[tx][ty + r * 8];
    }
}

// ---------------- pi GEMM v3: cp.async double-buffered staging -----------------
// Same math/layout as v2 (identical numerics); copy of chunk k+1 overlaps MMA of
// chunk k. Dynamic smem 60 KB; 2 blocks/SM.
__global__ void __launch_bounds__(256, 2)
pi3_kernel()
{
    pdl_sync();
    extern __shared__ __nv_bfloat16 smem[];
    __nv_bfloat16* Asm = smem;                         // [buf][hl][128][40]
    __nv_bfloat16* Bsm = smem + 2 * 2 * 128 * 40;      // [buf][hl][64][40]

    const int d = blockIdx.z;
    const __nv_bfloat16* Ah = g_ah + ((size_t)d << 17);
    const __nv_bfloat16* Al = g_al + ((size_t)d << 17);
    const __nv_bfloat16* Bh = g_wih + (size_t)d * NG * ND;
    const __nv_bfloat16* Bl = g_wil + (size_t)d * NG * ND;
    const int mBase = blockIdx.y * 128;
    const int nBase = blockIdx.x * 64;
    const int tid = threadIdx.x;

    // per-thread staging coordinates (fixed across chunks)
    const int ra0 = tid >> 2,           sa0 = (tid & 3) * 8;          // A rpt 0
    const int ra1 = (tid + 256) >> 2,   sa1 = sa0;                    // A rpt 1
    const int rb  = tid >> 2,           sb  = (tid & 3) * 8;          // B

    const uint32_t aBase = (uint32_t)__cvta_generic_to_shared(Asm);
    const uint32_t bBase = (uint32_t)__cvta_generic_to_shared(Bsm);

    auto stage = [&](int buf, int kk) {
        const int k0 = kk * 32;
        size_t soA0 = (size_t)(mBase + ra0) * ND + k0 + sa0;
        size_t soA1 = (size_t)(mBase + ra1) * ND + k0 + sa1;
        size_t soB  = (size_t)(nBase + rb)  * ND + k0 + sb;
        // As[buf][hl][r][seg]
        cpa16(aBase + (uint32_t)((((buf * 2 + 0) * 128 + ra0) * 40 + sa0) * 2), Ah + soA0);
        cpa16(aBase + (uint32_t)((((buf * 2 + 1) * 128 + ra0) * 40 + sa0) * 2), Al + soA0);
        cpa16(aBase + (uint32_t)((((buf * 2 + 0) * 128 + ra1) * 40 + sa1) * 2), Ah + soA1);
        cpa16(aBase + (uint32_t)((((buf * 2 + 1) * 128 + ra1) * 40 + sa1) * 2), Al + soA1);
        cpa16(bBase + (uint32_t)((((buf * 2 + 0) * 64 + rb) * 40 + sb) * 2), Bh + soB);
        cpa16(bBase + (uint32_t)((((buf * 2 + 1) * 64 + rb) * 40 + sb) * 2), Bl + soB);
        cpa_commit();
    };

    wmma::fragment<wmma::accumulator, 16, 16, 16, float> acc[2][2];
#pragma unroll
    for (int i = 0; i < 2; i++)
#pragma unroll
        for (int j = 0; j < 2; j++) wmma::fill_fragment(acc[i][j], 0.0f);

    const int w  = tid >> 5;
    const int wm = w >> 1;
    const int wn = w & 1;

    stage(0, 0);

    for (int kk = 0; kk < 16; kk++) {
        const int buf = kk & 1;
        if (kk < 15) {
            stage(buf ^ 1, kk + 1);
            asm volatile("cp.async.wait_group 1;");   // chunk kk landed
        } else {
            asm volatile("cp.async.wait_group 0;");
        }
        __syncthreads();

        const __nv_bfloat16* Ab0 = Asm + ((buf * 2 + 0) * 128) * 40;
        const __nv_bfloat16* Ab1 = Asm + ((buf * 2 + 1) * 128) * 40;
        const __nv_bfloat16* Bb0 = Bsm + ((buf * 2 + 0) * 64) * 40;
        const __nv_bfloat16* Bb1 = Bsm + ((buf * 2 + 1) * 64) * 40;

#pragma unroll
        for (int ks = 0; ks < 2; ks++) {
            wmma::fragment<wmma::matrix_a, 16, 16, 16, __nv_bfloat16, wmma::row_major> ah[2], al[2];
            wmma::fragment<wmma::matrix_b, 16, 16, 16, __nv_bfloat16, wmma::col_major> bh[2], bl[2];
#pragma unroll
            for (int i = 0; i < 2; i++) {
                wmma::load_matrix_sync(ah[i], Ab0 + (wm * 32 + i * 16) * 40 + ks * 16, 40);
                wmma::load_matrix_sync(al[i], Ab1 + (wm * 32 + i * 16) * 40 + ks * 16, 40);
            }
#pragma unroll
            for (int j = 0; j < 2; j++) {
                wmma::load_matrix_sync(bh[j], Bb0 + (wn * 32 + j * 16) * 40 + ks * 16, 40);
                wmma::load_matrix_sync(bl[j], Bb1 + (wn * 32 + j * 16) * 40 + ks * 16, 40);
            }
#pragma unroll
            for (int i = 0; i < 2; i++)
#pragma unroll
                for (int j = 0; j < 2; j++) {
                    wmma::mma_sync(acc[i][j], ah[i], bh[j], acc[i][j]);
                    wmma::mma_sync(acc[i][j], ah[i], bl[j], acc[i][j]);
                    wmma::mma_sync(acc[i][j], al[i], bh[j], acc[i][j]);
                }
        }
        __syncthreads();   // protect buf before overwrite two chunks later
    }

#pragma unroll
    for (int i = 0; i < 2; i++)
#pragma unroll
        for (int j = 0; j < 2; j++) {
            float* cp = g_pi + ((size_t)d * (NB * NT) + mBase + wm * 32 + i * 16) * NG
                             + nBase + wn * 32 + j * 16;
            wmma::store_matrix_sync(cp, acc[i][j], NG, wmma::mem_row_major);
        }
}

// ---------------- FUSED step: gates + cell + proj partial + last-block hfin ----
__global__ void __launch_bounds__(256, 4)
step_fused_kernel(const float* __restrict__ Ws_l,
                  const float* __restrict__ bs_l,
                  const int*   __restrict__ mask, int t)
{
    pdl_sync();
    __shared__ float sh[NB * NH];
    __shared__ float s_sm[8][4];
    __shared__ int isLast;
    const int d  = blockIdx.x >> 9;
    const int cb = (blockIdx.x & 511) * 8;
    const int td = d ? (NT - 1 - t) : t;
    const int tid = threadIdx.x;

    const float* hsrc = g_h + (size_t)d * NB * NH;
    for (int i = tid; i < NB * NH; i += 256) sh[i] = hsrc[i];
    __syncthreads();

    const int w = tid >> 5, lane = tid & 31;
    const int j = cb + w;
    const float* wbase = Ws_l + (size_t)d * NG * ND;

    float acc[4][4];
#pragma unroll
    for (int q = 0; q < 4; q++)
#pragma unroll
        for (int b = 0; b < 4; b++) acc[q][b] = 0.0f;

#pragma unroll
    for (int it = 0; it < 4; it++) {
        const int k = it * 128 + lane * 4;
        float4 hv0 = *(const float4*)&sh[0 * NH + k];
        float4 hv1 = *(const float4*)&sh[1 * NH + k];
        float4 hv2 = *(const float4*)&sh[2 * NH + k];
        float4 hv3 = *(const float4*)&sh[3 * NH + k];
#pragma unroll
        for (int q = 0; q < 4; q++) {
            float4 wv = *(const float4*)&wbase[(size_t)(q * NC + j) * ND + k];
            acc[q][0] += dot4(wv, hv0);
            acc[q][1] += dot4(wv, hv1);
            acc[q][2] += dot4(wv, hv2);
            acc[q][3] += dot4(wv, hv3);
        }
    }
#pragma unroll
    for (int off = 16; off > 0; off >>= 1)
#pragma unroll
        for (int q = 0; q < 4; q++)
#pragma unroll
            for (int b = 0; b < 4; b++)
                acc[q][b] += __shfl_xor_sync(0xffffffffu, acc[q][b], off);

    if (lane < 4) {
        const int b = lane;
        const float* pib = g_pi + (((size_t)d * NB + b) * NT + td) * NG;
        const float* bsd = bs_l + (size_t)d * NG;
        float gi = acc[0][b] + __ldcs(&pib[0 * NC + j]) + bsd[0 * NC + j];
        float gf = acc[1][b] + __ldcs(&pib[1 * NC + j]) + bsd[1 * NC + j];
        float gg = acc[2][b] + __ldcs(&pib[2 * NC + j]) + bsd[2 * NC + j];
        float go = acc[3][b] + __ldcs(&pib[3 * NC + j]) + bsd[3 * NC + j];

        const size_t ci = ((size_t)d * NB + b) * NC + j;
        float cold = g_c[ci];
        float cn = clip3(sigmoidf_(gi) * tanhf(gg) + sigmoidf_(gf) * cold);
        if (mask[b * NT + td] != 0) g_c[ci] = cn;
        s_sm[w][b] = sigmoidf_(go) * tanhf(cn);
    }
    __syncthreads();

    // ---- proj partial ----
    const float* wpT = g_wpT + (size_t)d * NC * NH + (size_t)cb * NH;
    float pa0[4] = {0.f, 0.f, 0.f, 0.f};
    float pa1[4] = {0.f, 0.f, 0.f, 0.f};
#pragma unroll
    for (int jl = 0; jl < 8; jl++) {
        float w0 = wpT[(size_t)jl * NH + tid];
        float w1 = wpT[(size_t)jl * NH + tid + 256];
#pragma unroll
        for (int b = 0; b < 4; b++) {
            pa0[b] += w0 * s_sm[jl][b];
            pa1[b] += w1 * s_sm[jl][b];
        }
    }
    const int part = (blockIdx.x & 511) >> 6;   // 0..7 (64 blocks per partition)
    float* dst = g_hpp[part] + (size_t)d * NB * NH;
#pragma unroll
    for (int b = 0; b < 4; b++) {
        atomicAdd(&dst[b * NH + tid],       pa0[b]);
        atomicAdd(&dst[b * NH + tid + 256], pa1[b]);
    }

    // ---- last-arriving block of this dir finalizes h ----
    __threadfence();
    __syncthreads();
    if (tid == 0)
        isLast = (atomicAdd(&g_fcnt[d], 1) == 511);
    __syncthreads();
    if (!isLast) return;

    const int base = d * (NB * NH);
    for (int idx = tid; idx < NB * NH; idx += 256) {
        float v = 0.0f;
#pragma unroll
        for (int k = 0; k < NPART; k++) {
            v += __ldcg(&g_hpp[k][base + idx]);   // fixed order, L2 reads
            g_hpp[k][base + idx] = 0.0f;          // ready for next step
        }
        v = clip3(v);
        const int b = idx >> 9, i = idx & 511;
        const size_t yi = (((size_t)d * NB + b) * NT + td) * NH + i;
        if (mask[b * NT + td] != 0) {
            g_h[base + idx] = v;
            g_y[yi] = v;
        } else {
            g_y[yi] = 0.0f;
        }
    }
    if (tid == 0) g_fcnt[d] = 0;   // reset for next launch / graph replay
}

// ---------------- finalize layer: skip-add, write output, feed next layer ------
__global__ void __launch_bounds__(512)
finalize_kernel(float* __restrict__ out, int l)
{
    pdl_sync();
    const int idx = blockIdx.x * blockDim.x + threadIdx.x;
    const int i  = idx & (NH - 1);
    const int tt = (idx >> 9) & (NT - 1);
    const int b  = (idx >> 15) & (NB - 1);
    const int d  = idx >> 17;
    float z = g_y[idx] + (l ? g_x[idx] : 0.0f);
    g_x[idx] = z;
    out[(((size_t)l * NB + b) * NT + tt) * (2 * NH) + d * NH + i] = z;
}

// ---------------- PDL launch helper ----------------
template <typename F, typename... Args>
static inline void launch_pdl(F kern, dim3 grid, dim3 block, size_t smem, Args... args)
{
    cudaLaunchConfig_t cfg = {};
    cfg.gridDim = grid;
    cfg.blockDim = block;
    cfg.dynamicSmemBytes = smem;
    cfg.stream = 0;
    cudaLaunchAttribute attr[1];
    attr[0].id = cudaLaunchAttributeProgrammaticStreamSerialization;
    attr[0].val.programmaticStreamSerializationAllowed = 1;
    cfg.attrs = attr;
    cfg.numAttrs = 1;
    cudaLaunchKernelEx(&cfg, kern, args...);
}

// ---------------- launcher ----------------
extern "C" void kernel_launch(void* const* d_in, const int* in_sizes, int n_in,
                              void* d_out, int out_size)
{
    const float* inputs = (const float*)d_in[0];   // (4,64,512)
    const int*   mask   = (const int*)  d_in[1];   // (4,64)
    const float* Wi     = (const float*)d_in[2];   // (2,2,16384,512)
    const float* Ws     = (const float*)d_in[3];   // (2,2,16384,512)
    const float* bs     = (const float*)d_in[4];   // (2,2,16384)
    const float* Wp     = (const float*)d_in[5];   // (2,2,512,4096)
    float* out = (float*)d_out;                    // (2,4,64,1024)

    // idempotent, host-side (not a graph node); called every launch for determinism
    cudaFuncSetAttribute(pi3_kernel,
                         cudaFuncAttributeMaxDynamicSharedMemorySize,
                         PI_SMEM_BYTES);

    const int wiBlocks = (int)(WI_ELEMS / 8 / 256);  // 8192
    const int aBlocks  = (int)(A_ELEMS / 8 / 256);   // 128

    for (int l = 0; l < NL; l++) {
        const float* Wi_l = Wi + (size_t)l * 2 * NG * ND;
        const float* Ws_l = Ws + (size_t)l * 2 * NG * ND;
        const float* bs_l = bs + (size_t)l * 2 * NG;
        const float* Wp_l = Wp + (size_t)l * 2 * NH * NC;

        launch_pdl(init_state_kernel, dim3(144), dim3(256), 0);
        launch_pdl(convert_wi_kernel, dim3(wiBlocks), dim3(256), 0, Wi_l);
        launch_pdl(convert_a_kernel, dim3(aBlocks), dim3(256), 0, inputs, l);
        launch_pdl(transpose_wp_kernel, dim3(128, 16, 2), dim3(256), 0, Wp_l);

        dim3 gp(NG / 64, (NB * NT) / 128, 2);
        launch_pdl(pi3_kernel, gp, dim3(256), (size_t)PI_SMEM_BYTES);

        for (int t = 0; t < NT; t++)
            launch_pdl(step_fused_kernel, dim3(1024), dim3(256), 0, Ws_l, bs_l, mask, t);

        launch_pdl(finalize_kernel, dim3(512), dim3(512), 0, out, l);
    }
}

// round 16
// speedup vs baseline: 1.4313x; 1.4313x over previous
#include <cuda_runtime.h>
#include <cuda_bf16.h>
#include <mma.h>
#include <math.h>
#include <cstdint>

using namespace nvcuda;

// ---------------- problem constants ----------------
#define NL 2          // layers
#define NB 4          // batch
#define NT 64         // time
#define ND 512        // input dim
#define NH 512        // hidden/proj dim
#define NC 4096       // cell dim
#define NG (4*NC)     // 16384 gate rows per dir
#define CLIPV 3.0f
#define NPART 32      // proj-partial partitions (16 blocks add per partition)
#define WI_ELEMS ((size_t)2 * NG * ND)      // 16,777,216 per layer
#define A_ELEMS  ((size_t)2 * NB * NT * NH) // 262,144 (both dirs)
// pi dynamic smem: As[2buf][2hl][128][40] + Bs[2buf][2hl][64][40], bf16
#define PI_SMEM_ELEMS (2*2*128*40 + 2*2*64*40)
#define PI_SMEM_BYTES (PI_SMEM_ELEMS * 2)   // 61440

// ---------------- device scratch (static allocation: allowed) ----------------
__device__ __align__(16) float g_pi[(size_t)2 * NB * NT * NG];   // 32 MiB
__device__ __align__(16) float g_x [(size_t)2 * NB * NT * NH];
__device__ __align__(16) float g_y [(size_t)2 * NB * NT * NH];
__device__ __align__(16) float g_c [(size_t)2 * NB * NC];
__device__ __align__(16) float g_h [(size_t)2 * NB * NH];
__device__ __align__(16) __nv_bfloat16 g_wih[WI_ELEMS];
__device__ __align__(16) __nv_bfloat16 g_wil[WI_ELEMS];
__device__ __align__(16) __nv_bfloat16 g_ah[A_ELEMS];
__device__ __align__(16) __nv_bfloat16 g_al[A_ELEMS];
__device__ __align__(16) float g_wpT[(size_t)2 * NC * NH];       // 16.8 MB
// proj partial accumulators: [parity][partition][(d*NB+b)*NH + i]
// zero-initialized; steady state re-zeroed by hfin after each read
__device__ __align__(16) float g_hpp[2][NPART][2 * NB * NH];     // 1 MB

__device__ __forceinline__ void pdl_sync() {
#if defined(__CUDA_ARCH__) && (__CUDA_ARCH__ >= 900)
    cudaGridDependencySynchronize();
#endif
}

__device__ __forceinline__ float dot4(float4 a, float4 b) {
    return a.x*b.x + a.y*b.y + a.z*b.z + a.w*b.w;
}
__device__ __forceinline__ float sigmoidf_(float x) { return 1.0f / (1.0f + expf(-x)); }
__device__ __forceinline__ float clip3(float x)     { return fminf(CLIPV, fmaxf(-CLIPV, x)); }

__device__ __forceinline__ void cpa16(uint32_t dst, const void* src) {
    asm volatile("cp.async.cg.shared.global [%0], [%1], 16;" :: "r"(dst), "l"(src));
}
__device__ __forceinline__ void cpa_commit() {
    asm volatile("cp.async.commit_group;");
}

// ---------------- init: zero h and c (reference resets per layer/direction) ----
__global__ void init_state_kernel() {
    pdl_sync();
    int idx = blockIdx.x * blockDim.x + threadIdx.x;
    if (idx < 2 * NB * NC) g_c[idx] = 0.0f;
    if (idx < 2 * NB * NH) g_h[idx] = 0.0f;
}

// ---------------- conversion: Wi fp32 -> split-bf16 hi/lo ----------------------
__global__ void __launch_bounds__(256)
convert_wi_kernel(const float* __restrict__ Wi_l)
{
    pdl_sync();
    size_t idx = ((size_t)blockIdx.x * 256 + threadIdx.x) * 8;
    if (idx >= WI_ELEMS) return;
    float4 a = __ldcs((const float4*)(Wi_l + idx));
    float4 b = __ldcs((const float4*)(Wi_l + idx + 4));
    float v[8] = {a.x, a.y, a.z, a.w, b.x, b.y, b.z, b.w};
    __align__(16) __nv_bfloat16 hi[8], lo[8];
#pragma unroll
    for (int q = 0; q < 8; q++) {
        hi[q] = __float2bfloat16(v[q]);
        lo[q] = __float2bfloat16(v[q] - __bfloat162float(hi[q]));
    }
    *(uint4*)(g_wih + idx) = *(const uint4*)hi;
    *(uint4*)(g_wil + idx) = *(const uint4*)lo;
}

// ---------------- conversion: A (inputs or g_x) -> split-bf16 hi/lo ------------
__global__ void __launch_bounds__(256)
convert_a_kernel(const float* __restrict__ x0, int l)
{
    pdl_sync();
    size_t idx = ((size_t)blockIdx.x * 256 + threadIdx.x) * 8;
    if (idx >= A_ELEMS) return;
    const size_t d   = idx >> 17;
    const size_t off = idx & 131071;
    const float* src = l ? (g_x + (d << 17) + off) : (x0 + off);
    float4 a = *(const float4*)src;
    float4 b = *(const float4*)(src + 4);
    float v[8] = {a.x, a.y, a.z, a.w, b.x, b.y, b.z, b.w};
    __align__(16) __nv_bfloat16 hi[8], lo[8];
#pragma unroll
    for (int q = 0; q < 8; q++) {
        hi[q] = __float2bfloat16(v[q]);
        lo[q] = __float2bfloat16(v[q] - __bfloat162float(hi[q]));
    }
    *(uint4*)(g_ah + idx) = *(const uint4*)hi;
    *(uint4*)(g_al + idx) = *(const uint4*)lo;
}

// ---------------- transpose Wp: (2,512,4096) -> g_wpT (2,4096,512) -------------
__global__ void __launch_bounds__(256)
transpose_wp_kernel(const float* __restrict__ Wp_l)
{
    pdl_sync();
    __shared__ float tile[32][33];
    const int d = blockIdx.z;
    const int jb = blockIdx.x * 32;
    const int ib = blockIdx.y * 32;
    const int tx = threadIdx.x & 31, ty = threadIdx.x >> 5;
    const float* src = Wp_l + (size_t)d * NH * NC;
#pragma unroll
    for (int r = 0; r < 4; r++) {
        int i = ib + ty + r * 8;
        tile[ty + r * 8][tx] = src[(size_t)i * NC + jb + tx];
    }
    __syncthreads();
    float* dst = g_wpT + (size_t)d * NC * NH;
#pragma unroll
    for (int r = 0; r < 4; r++) {
        int j = jb + ty + r * 8;
        dst[(size_t)j * NH + ib + tx] = tile[tx][ty + r * 8];
    }
}

// ---------------- pi GEMM v3: cp.async double-buffered staging -----------------
// Same math/layout as v2 (identical numerics); copy of chunk k+1 overlaps MMA of
// chunk k. Dynamic smem 60 KB; 2 blocks/SM.
__global__ void __launch_bounds__(256, 2)
pi3_kernel()
{
    pdl_sync();
    extern __shared__ __nv_bfloat16 smem[];
    __nv_bfloat16* Asm = smem;                         // [buf][hl][128][40]
    __nv_bfloat16* Bsm = smem + 2 * 2 * 128 * 40;      // [buf][hl][64][40]

    const int d = blockIdx.z;
    const __nv_bfloat16* Ah = g_ah + ((size_t)d << 17);
    const __nv_bfloat16* Al = g_al + ((size_t)d << 17);
    const __nv_bfloat16* Bh = g_wih + (size_t)d * NG * ND;
    const __nv_bfloat16* Bl = g_wil + (size_t)d * NG * ND;
    const int mBase = blockIdx.y * 128;
    const int nBase = blockIdx.x * 64;
    const int tid = threadIdx.x;

    const int ra0 = tid >> 2,           sa0 = (tid & 3) * 8;
    const int ra1 = (tid + 256) >> 2,   sa1 = sa0;
    const int rb  = tid >> 2,           sb  = (tid & 3) * 8;

    const uint32_t aBase = (uint32_t)__cvta_generic_to_shared(Asm);
    const uint32_t bBase = (uint32_t)__cvta_generic_to_shared(Bsm);

    auto stage = [&](int buf, int kk) {
        const int k0 = kk * 32;
        size_t soA0 = (size_t)(mBase + ra0) * ND + k0 + sa0;
        size_t soA1 = (size_t)(mBase + ra1) * ND + k0 + sa1;
        size_t soB  = (size_t)(nBase + rb)  * ND + k0 + sb;
        cpa16(aBase + (uint32_t)((((buf * 2 + 0) * 128 + ra0) * 40 + sa0) * 2), Ah + soA0);
        cpa16(aBase + (uint32_t)((((buf * 2 + 1) * 128 + ra0) * 40 + sa0) * 2), Al + soA0);
        cpa16(aBase + (uint32_t)((((buf * 2 + 0) * 128 + ra1) * 40 + sa1) * 2), Ah + soA1);
        cpa16(aBase + (uint32_t)((((buf * 2 + 1) * 128 + ra1) * 40 + sa1) * 2), Al + soA1);
        cpa16(bBase + (uint32_t)((((buf * 2 + 0) * 64 + rb) * 40 + sb) * 2), Bh + soB);
        cpa16(bBase + (uint32_t)((((buf * 2 + 1) * 64 + rb) * 40 + sb) * 2), Bl + soB);
        cpa_commit();
    };

    wmma::fragment<wmma::accumulator, 16, 16, 16, float> acc[2][2];
#pragma unroll
    for (int i = 0; i < 2; i++)
#pragma unroll
        for (int j = 0; j < 2; j++) wmma::fill_fragment(acc[i][j], 0.0f);

    const int w  = tid >> 5;
    const int wm = w >> 1;
    const int wn = w & 1;

    stage(0, 0);

    for (int kk = 0; kk < 16; kk++) {
        const int buf = kk & 1;
        if (kk < 15) {
            stage(buf ^ 1, kk + 1);
            asm volatile("cp.async.wait_group 1;");
        } else {
            asm volatile("cp.async.wait_group 0;");
        }
        __syncthreads();

        const __nv_bfloat16* Ab0 = Asm + ((buf * 2 + 0) * 128) * 40;
        const __nv_bfloat16* Ab1 = Asm + ((buf * 2 + 1) * 128) * 40;
        const __nv_bfloat16* Bb0 = Bsm + ((buf * 2 + 0) * 64) * 40;
        const __nv_bfloat16* Bb1 = Bsm + ((buf * 2 + 1) * 64) * 40;

#pragma unroll
        for (int ks = 0; ks < 2; ks++) {
            wmma::fragment<wmma::matrix_a, 16, 16, 16, __nv_bfloat16, wmma::row_major> ah[2], al[2];
            wmma::fragment<wmma::matrix_b, 16, 16, 16, __nv_bfloat16, wmma::col_major> bh[2], bl[2];
#pragma unroll
            for (int i = 0; i < 2; i++) {
                wmma::load_matrix_sync(ah[i], Ab0 + (wm * 32 + i * 16) * 40 + ks * 16, 40);
                wmma::load_matrix_sync(al[i], Ab1 + (wm * 32 + i * 16) * 40 + ks * 16, 40);
            }
#pragma unroll
            for (int j = 0; j < 2; j++) {
                wmma::load_matrix_sync(bh[j], Bb0 + (wn * 32 + j * 16) * 40 + ks * 16, 40);
                wmma::load_matrix_sync(bl[j], Bb1 + (wn * 32 + j * 16) * 40 + ks * 16, 40);
            }
#pragma unroll
            for (int i = 0; i < 2; i++)
#pragma unroll
                for (int j = 0; j < 2; j++) {
                    wmma::mma_sync(acc[i][j], ah[i], bh[j], acc[i][j]);
                    wmma::mma_sync(acc[i][j], ah[i], bl[j], acc[i][j]);
                    wmma::mma_sync(acc[i][j], al[i], bh[j], acc[i][j]);
                }
        }
        __syncthreads();
    }

#pragma unroll
    for (int i = 0; i < 2; i++)
#pragma unroll
        for (int j = 0; j < 2; j++) {
            float* cp = g_pi + ((size_t)d * (NB * NT) + mBase + wm * 32 + i * 16) * NG
                             + nBase + wn * 32 + j * 16;
            wmma::store_matrix_sync(cp, acc[i][j], NG, wmma::mem_row_major);
        }
}

// ---------------- FUSED step (R12 verbatim): gates + cell + proj partial -------
// fire-and-forget; partition (blk&511)>>4 of the parity-(t&1) accumulator.
__global__ void __launch_bounds__(256, 4)
step_fused_kernel(const float* __restrict__ Ws_l,
                  const float* __restrict__ bs_l,
                  const int*   __restrict__ mask, int t)
{
    pdl_sync();
    __shared__ float sh[NB * NH];
    __shared__ float s_sm[8][4];
    const int d  = blockIdx.x >> 9;
    const int cb = (blockIdx.x & 511) * 8;
    const int td = d ? (NT - 1 - t) : t;
    const int tid = threadIdx.x;

    const float* hsrc = g_h + (size_t)d * NB * NH;
    for (int i = tid; i < NB * NH; i += 256) sh[i] = hsrc[i];
    __syncthreads();

    const int w = tid >> 5, lane = tid & 31;
    const int j = cb + w;
    const float* wbase = Ws_l + (size_t)d * NG * ND;

    float acc[4][4];
#pragma unroll
    for (int q = 0; q < 4; q++)
#pragma unroll
        for (int b = 0; b < 4; b++) acc[q][b] = 0.0f;

#pragma unroll
    for (int it = 0; it < 4; it++) {
        const int k = it * 128 + lane * 4;
        float4 hv0 = *(const float4*)&sh[0 * NH + k];
        float4 hv1 = *(const float4*)&sh[1 * NH + k];
        float4 hv2 = *(const float4*)&sh[2 * NH + k];
        float4 hv3 = *(const float4*)&sh[3 * NH + k];
#pragma unroll
        for (int q = 0; q < 4; q++) {
            float4 wv = *(const float4*)&wbase[(size_t)(q * NC + j) * ND + k];
            acc[q][0] += dot4(wv, hv0);
            acc[q][1] += dot4(wv, hv1);
            acc[q][2] += dot4(wv, hv2);
            acc[q][3] += dot4(wv, hv3);
        }
    }
#pragma unroll
    for (int off = 16; off > 0; off >>= 1)
#pragma unroll
        for (int q = 0; q < 4; q++)
#pragma unroll
            for (int b = 0; b < 4; b++)
                acc[q][b] += __shfl_xor_sync(0xffffffffu, acc[q][b], off);

    if (lane < 4) {
        const int b = lane;
        const float* pib = g_pi + (((size_t)d * NB + b) * NT + td) * NG;
        const float* bsd = bs_l + (size_t)d * NG;
        float gi = acc[0][b] + __ldcs(&pib[0 * NC + j]) + bsd[0 * NC + j];
        float gf = acc[1][b] + __ldcs(&pib[1 * NC + j]) + bsd[1 * NC + j];
        float gg = acc[2][b] + __ldcs(&pib[2 * NC + j]) + bsd[2 * NC + j];
        float go = acc[3][b] + __ldcs(&pib[3 * NC + j]) + bsd[3 * NC + j];

        const size_t ci = ((size_t)d * NB + b) * NC + j;
        float cold = g_c[ci];
        float cn = clip3(sigmoidf_(gi) * tanhf(gg) + sigmoidf_(gf) * cold);
        if (mask[b * NT + td] != 0) g_c[ci] = cn;
        s_sm[w][b] = sigmoidf_(go) * tanhf(cn);
    }
    __syncthreads();

    // ---- proj partial: outputs i0 = tid, i1 = tid + 256 ----
    const float* wpT = g_wpT + (size_t)d * NC * NH + (size_t)cb * NH;
    float pa0[4] = {0.f, 0.f, 0.f, 0.f};
    float pa1[4] = {0.f, 0.f, 0.f, 0.f};
#pragma unroll
    for (int jl = 0; jl < 8; jl++) {
        float w0 = wpT[(size_t)jl * NH + tid];
        float w1 = wpT[(size_t)jl * NH + tid + 256];
#pragma unroll
        for (int b = 0; b < 4; b++) {
            pa0[b] += w0 * s_sm[jl][b];
            pa1[b] += w1 * s_sm[jl][b];
        }
    }
    const int part = (blockIdx.x & 511) >> 4;   // 0..31 (16 blocks per partition)
    float* dst = g_hpp[t & 1][part] + (size_t)d * NB * NH;
#pragma unroll
    for (int b = 0; b < 4; b++) {
        atomicAdd(&dst[b * NH + tid],       pa0[b]);
        atomicAdd(&dst[b * NH + tid + 256], pa1[b]);
    }
}

// ---------------- hfin (R12 verbatim): sum partials -> h, y; re-zero -----------
__global__ void __launch_bounds__(256)
hfin_kernel(const int* __restrict__ mask, int t)
{
    pdl_sync();
    const int idx = blockIdx.x * 256 + threadIdx.x;   // 0..4095
    const int d = idx >> 11;
    const int b = (idx >> 9) & 3;
    const int i = idx & 511;
    const int td = d ? (NT - 1 - t) : t;
    const int par = t & 1;

    float v = 0.0f;
#pragma unroll
    for (int k = 0; k < NPART; k++) {
        v += g_hpp[par][k][idx];
        g_hpp[par][k][idx] = 0.0f;    // ready for step t+2
    }
    v = clip3(v);
    const size_t yi = (((size_t)d * NB + b) * NT + td) * NH + i;
    if (mask[b * NT + td] != 0) {
        g_h[idx] = v;
        g_y[yi] = v;
    } else {
        g_y[yi] = 0.0f;
    }
}

// ---------------- finalize layer: skip-add, write output, feed next layer ------
__global__ void __launch_bounds__(512)
finalize_kernel(float* __restrict__ out, int l)
{
    pdl_sync();
    const int idx = blockIdx.x * blockDim.x + threadIdx.x;
    const int i  = idx & (NH - 1);
    const int tt = (idx >> 9) & (NT - 1);
    const int b  = (idx >> 15) & (NB - 1);
    const int d  = idx >> 17;
    float z = g_y[idx] + (l ? g_x[idx] : 0.0f);
    g_x[idx] = z;
    out[(((size_t)l * NB + b) * NT + tt) * (2 * NH) + d * NH + i] = z;
}

// ---------------- PDL launch helper ----------------
template <typename F, typename... Args>
static inline void launch_pdl(F kern, dim3 grid, dim3 block, size_t smem, Args... args)
{
    cudaLaunchConfig_t cfg = {};
    cfg.gridDim = grid;
    cfg.blockDim = block;
    cfg.dynamicSmemBytes = smem;
    cfg.stream = 0;
    cudaLaunchAttribute attr[1];
    attr[0].id = cudaLaunchAttributeProgrammaticStreamSerialization;
    attr[0].val.programmaticStreamSerializationAllowed = 1;
    cfg.attrs = attr;
    cfg.numAttrs = 1;
    cudaLaunchKernelEx(&cfg, kern, args...);
}

// ---------------- launcher ----------------
extern "C" void kernel_launch(void* const* d_in, const int* in_sizes, int n_in,
                              void* d_out, int out_size)
{
    const float* inputs = (const float*)d_in[0];   // (4,64,512)
    const int*   mask   = (const int*)  d_in[1];   // (4,64)
    const float* Wi     = (const float*)d_in[2];   // (2,2,16384,512)
    const float* Ws     = (const float*)d_in[3];   // (2,2,16384,512)
    const float* bs     = (const float*)d_in[4];   // (2,2,16384)
    const float* Wp     = (const float*)d_in[5];   // (2,2,512,4096)
    float* out = (float*)d_out;                    // (2,4,64,1024)

    // idempotent, host-side; called every launch for determinism
    cudaFuncSetAttribute(pi3_kernel,
                         cudaFuncAttributeMaxDynamicSharedMemorySize,
                         PI_SMEM_BYTES);

    const int wiBlocks = (int)(WI_ELEMS / 8 / 256);  // 8192
    const int aBlocks  = (int)(A_ELEMS / 8 / 256);   // 128

    for (int l = 0; l < NL; l++) {
        const float* Wi_l = Wi + (size_t)l * 2 * NG * ND;
        const float* Ws_l = Ws + (size_t)l * 2 * NG * ND;
        const float* bs_l = bs + (size_t)l * 2 * NG;
        const float* Wp_l = Wp + (size_t)l * 2 * NH * NC;

        launch_pdl(init_state_kernel, dim3(144), dim3(256), 0);
        launch_pdl(convert_wi_kernel, dim3(wiBlocks), dim3(256), 0, Wi_l);
        launch_pdl(convert_a_kernel, dim3(aBlocks), dim3(256), 0, inputs, l);
        launch_pdl(transpose_wp_kernel, dim3(128, 16, 2), dim3(256), 0, Wp_l);

        dim3 gp(NG / 64, (NB * NT) / 128, 2);
        launch_pdl(pi3_kernel, gp, dim3(256), (size_t)PI_SMEM_BYTES);

        for (int t = 0; t < NT; t++) {
            launch_pdl(step_fused_kernel, dim3(1024), dim3(256), 0, Ws_l, bs_l, mask, t);
            launch_pdl(hfin_kernel, dim3(16), dim3(256), 0, mask, t);
        }
        launch_pdl(finalize_kernel, dim3(512), dim3(512), 0, out, l);
    }
}

// round 17
// speedup vs baseline: 1.5210x; 1.0626x over previous
#include <cuda_runtime.h>
#include <cuda_bf16.h>
#include <cuda_fp16.h>
#include <mma.h>
#include <math.h>
#include <cstdint>

using namespace nvcuda;

// ---------------- problem constants ----------------
#define NL 2          // layers
#define NB 4          // batch
#define NT 64         // time
#define ND 512        // input dim
#define NH 512        // hidden/proj dim
#define NC 4096       // cell dim
#define NG (4*NC)     // 16384 gate rows per dir
#define CLIPV 3.0f
#define NPART 32      // proj-partial partitions (16 blocks add per partition)
#define WI_ELEMS ((size_t)2 * NG * ND)      // 16,777,216 per layer
#define WS_ELEMS ((size_t)2 * NG * ND)      // 16,777,216 per layer
#define A_ELEMS  ((size_t)2 * NB * NT * NH) // 262,144 (both dirs)
// pi dynamic smem: As[2buf][2hl][128][40] + Bs[2buf][2hl][64][40], bf16
#define PI_SMEM_ELEMS (2*2*128*40 + 2*2*64*40)
#define PI_SMEM_BYTES (PI_SMEM_ELEMS * 2)   // 61440

// ---------------- device scratch (static allocation: allowed) ----------------
__device__ __align__(16) float g_pi[(size_t)2 * NB * NT * NG];   // 32 MiB
__device__ __align__(16) float g_x [(size_t)2 * NB * NT * NH];
__device__ __align__(16) float g_y [(size_t)2 * NB * NT * NH];
__device__ __align__(16) float g_c [(size_t)2 * NB * NC];
__device__ __align__(16) float g_h [(size_t)2 * NB * NH];
__device__ __align__(16) __nv_bfloat16 g_wih[WI_ELEMS];
__device__ __align__(16) __nv_bfloat16 g_wil[WI_ELEMS];
__device__ __align__(16) __nv_bfloat16 g_ah[A_ELEMS];
__device__ __align__(16) __nv_bfloat16 g_al[A_ELEMS];
__device__ __align__(16) __half g_wsh[WS_ELEMS];                 // fp16 Ws, 33.5 MB
__device__ __align__(16) float g_wpT[(size_t)2 * NC * NH];       // 16.8 MB
// proj partial accumulators: [parity][partition][(d*NB+b)*NH + i]
__device__ __align__(16) float g_hpp[2][NPART][2 * NB * NH];     // 1 MB

__device__ __forceinline__ void pdl_sync() {
#if defined(__CUDA_ARCH__) && (__CUDA_ARCH__ >= 900)
    cudaGridDependencySynchronize();
#endif
}

__device__ __forceinline__ float dot4(float4 a, float4 b) {
    return a.x*b.x + a.y*b.y + a.z*b.z + a.w*b.w;
}
__device__ __forceinline__ float sigmoidf_(float x) { return 1.0f / (1.0f + expf(-x)); }
__device__ __forceinline__ float clip3(float x)     { return fminf(CLIPV, fmaxf(-CLIPV, x)); }

// 4 halves (uint2) -> float4
__device__ __forceinline__ float4 h4tof4(uint2 u) {
    float2 a = __half22float2(*(const __half2*)&u.x);
    float2 b = __half22float2(*(const __half2*)&u.y);
    return make_float4(a.x, a.y, b.x, b.y);
}

__device__ __forceinline__ void cpa16(uint32_t dst, const void* src) {
    asm volatile("cp.async.cg.shared.global [%0], [%1], 16;" :: "r"(dst), "l"(src));
}
__device__ __forceinline__ void cpa_commit() {
    asm volatile("cp.async.commit_group;");
}

// ---------------- init: zero h and c (reference resets per layer/direction) ----
__global__ void init_state_kernel() {
    pdl_sync();
    int idx = blockIdx.x * blockDim.x + threadIdx.x;
    if (idx < 2 * NB * NC) g_c[idx] = 0.0f;
    if (idx < 2 * NB * NH) g_h[idx] = 0.0f;
}

// ---------------- conversion: Wi fp32 -> split-bf16 hi/lo ----------------------
__global__ void __launch_bounds__(256)
convert_wi_kernel(const float* __restrict__ Wi_l)
{
    pdl_sync();
    size_t idx = ((size_t)blockIdx.x * 256 + threadIdx.x) * 8;
    if (idx >= WI_ELEMS) return;
    float4 a = __ldcs((const float4*)(Wi_l + idx));
    float4 b = __ldcs((const float4*)(Wi_l + idx + 4));
    float v[8] = {a.x, a.y, a.z, a.w, b.x, b.y, b.z, b.w};
    __align__(16) __nv_bfloat16 hi[8], lo[8];
#pragma unroll
    for (int q = 0; q < 8; q++) {
        hi[q] = __float2bfloat16(v[q]);
        lo[q] = __float2bfloat16(v[q] - __bfloat162float(hi[q]));
    }
    *(uint4*)(g_wih + idx) = *(const uint4*)hi;
    *(uint4*)(g_wil + idx) = *(const uint4*)lo;
}

// ---------------- conversion: Ws fp32 -> fp16 (once per layer) -----------------
__global__ void __launch_bounds__(256)
convert_ws_kernel(const float* __restrict__ Ws_l)
{
    pdl_sync();
    size_t idx = ((size_t)blockIdx.x * 256 + threadIdx.x) * 8;
    if (idx >= WS_ELEMS) return;
    float4 a = __ldcs((const float4*)(Ws_l + idx));
    float4 b = __ldcs((const float4*)(Ws_l + idx + 4));
    __half2 h0 = __floats2half2_rn(a.x, a.y);
    __half2 h1 = __floats2half2_rn(a.z, a.w);
    __half2 h2 = __floats2half2_rn(b.x, b.y);
    __half2 h3 = __floats2half2_rn(b.z, b.w);
    uint4 u;
    u.x = *(const unsigned*)&h0; u.y = *(const unsigned*)&h1;
    u.z = *(const unsigned*)&h2; u.w = *(const unsigned*)&h3;
    *(uint4*)(g_wsh + idx) = u;
}

// ---------------- conversion: A (inputs or g_x) -> split-bf16 hi/lo ------------
__global__ void __launch_bounds__(256)
convert_a_kernel(const float* __restrict__ x0, int l)
{
    pdl_sync();
    size_t idx = ((size_t)blockIdx.x * 256 + threadIdx.x) * 8;
    if (idx >= A_ELEMS) return;
    const size_t d   = idx >> 17;
    const size_t off = idx & 131071;
    const float* src = l ? (g_x + (d << 17) + off) : (x0 + off);
    float4 a = *(const float4*)src;
    float4 b = *(const float4*)(src + 4);
    float v[8] = {a.x, a.y, a.z, a.w, b.x, b.y, b.z, b.w};
    __align__(16) __nv_bfloat16 hi[8], lo[8];
#pragma unroll
    for (int q = 0; q < 8; q++) {
        hi[q] = __float2bfloat16(v[q]);
        lo[q] = __float2bfloat16(v[q] - __bfloat162float(hi[q]));
    }
    *(uint4*)(g_ah + idx) = *(const uint4*)hi;
    *(uint4*)(g_al + idx) = *(const uint4*)lo;
}

// ---------------- transpose Wp: (2,512,4096) -> g_wpT (2,4096,512) -------------
__global__ void __launch_bounds__(256)
transpose_wp_kernel(const float* __restrict__ Wp_l)
{
    pdl_sync();
    __shared__ float tile[32][33];
    const int d = blockIdx.z;
    const int jb = blockIdx.x * 32;
    const int ib = blockIdx.y * 32;
    const int tx = threadIdx.x & 31, ty = threadIdx.x >> 5;
    const float* src = Wp_l + (size_t)d * NH * NC;
#pragma unroll
    for (int r = 0; r < 4; r++) {
        int i = ib + ty + r * 8;
        tile[ty + r * 8][tx] = src[(size_t)i * NC + jb + tx];
    }
    __syncthreads();
    float* dst = g_wpT + (size_t)d * NC * NH;
#pragma unroll
    for (int r = 0; r < 4; r++) {
        int j = jb + ty + r * 8;
        dst[(size_t)j * NH + ib + tx] = tile[tx][ty + r * 8];
    }
}

// ---------------- pi GEMM v3: cp.async double-buffered staging -----------------
__global__ void __launch_bounds__(256, 2)
pi3_kernel()
{
    pdl_sync();
    extern __shared__ __nv_bfloat16 smem[];
    __nv_bfloat16* Asm = smem;                         // [buf][hl][128][40]
    __nv_bfloat16* Bsm = smem + 2 * 2 * 128 * 40;      // [buf][hl][64][40]

    const int d = blockIdx.z;
    const __nv_bfloat16* Ah = g_ah + ((size_t)d << 17);
    const __nv_bfloat16* Al = g_al + ((size_t)d << 17);
    const __nv_bfloat16* Bh = g_wih + (size_t)d * NG * ND;
    const __nv_bfloat16* Bl = g_wil + (size_t)d * NG * ND;
    const int mBase = blockIdx.y * 128;
    const int nBase = blockIdx.x * 64;
    const int tid = threadIdx.x;

    const int ra0 = tid >> 2,           sa0 = (tid & 3) * 8;
    const int ra1 = (tid + 256) >> 2,   sa1 = sa0;
    const int rb  = tid >> 2,           sb  = (tid & 3) * 8;

    const uint32_t aBase = (uint32_t)__cvta_generic_to_shared(Asm);
    const uint32_t bBase = (uint32_t)__cvta_generic_to_shared(Bsm);

    auto stage = [&](int buf, int kk) {
        const int k0 = kk * 32;
        size_t soA0 = (size_t)(mBase + ra0) * ND + k0 + sa0;
        size_t soA1 = (size_t)(mBase + ra1) * ND + k0 + sa1;
        size_t soB  = (size_t)(nBase + rb)  * ND + k0 + sb;
        cpa16(aBase + (uint32_t)((((buf * 2 + 0) * 128 + ra0) * 40 + sa0) * 2), Ah + soA0);
        cpa16(aBase + (uint32_t)((((buf * 2 + 1) * 128 + ra0) * 40 + sa0) * 2), Al + soA0);
        cpa16(aBase + (uint32_t)((((buf * 2 + 0) * 128 + ra1) * 40 + sa1) * 2), Ah + soA1);
        cpa16(aBase + (uint32_t)((((buf * 2 + 1) * 128 + ra1) * 40 + sa1) * 2), Al + soA1);
        cpa16(bBase + (uint32_t)((((buf * 2 + 0) * 64 + rb) * 40 + sb) * 2), Bh + soB);
        cpa16(bBase + (uint32_t)((((buf * 2 + 1) * 64 + rb) * 40 + sb) * 2), Bl + soB);
        cpa_commit();
    };

    wmma::fragment<wmma::accumulator, 16, 16, 16, float> acc[2][2];
#pragma unroll
    for (int i = 0; i < 2; i++)
#pragma unroll
        for (int j = 0; j < 2; j++) wmma::fill_fragment(acc[i][j], 0.0f);

    const int w  = tid >> 5;
    const int wm = w >> 1;
    const int wn = w & 1;

    stage(0, 0);

    for (int kk = 0; kk < 16; kk++) {
        const int buf = kk & 1;
        if (kk < 15) {
            stage(buf ^ 1, kk + 1);
            asm volatile("cp.async.wait_group 1;");
        } else {
            asm volatile("cp.async.wait_group 0;");
        }
        __syncthreads();

        const __nv_bfloat16* Ab0 = Asm + ((buf * 2 + 0) * 128) * 40;
        const __nv_bfloat16* Ab1 = Asm + ((buf * 2 + 1) * 128) * 40;
        const __nv_bfloat16* Bb0 = Bsm + ((buf * 2 + 0) * 64) * 40;
        const __nv_bfloat16* Bb1 = Bsm + ((buf * 2 + 1) * 64) * 40;

#pragma unroll
        for (int ks = 0; ks < 2; ks++) {
            wmma::fragment<wmma::matrix_a, 16, 16, 16, __nv_bfloat16, wmma::row_major> ah[2], al[2];
            wmma::fragment<wmma::matrix_b, 16, 16, 16, __nv_bfloat16, wmma::col_major> bh[2], bl[2];
#pragma unroll
            for (int i = 0; i < 2; i++) {
                wmma::load_matrix_sync(ah[i], Ab0 + (wm * 32 + i * 16) * 40 + ks * 16, 40);
                wmma::load_matrix_sync(al[i], Ab1 + (wm * 32 + i * 16) * 40 + ks * 16, 40);
            }
#pragma unroll
            for (int j = 0; j < 2; j++) {
                wmma::load_matrix_sync(bh[j], Bb0 + (wn * 32 + j * 16) * 40 + ks * 16, 40);
                wmma::load_matrix_sync(bl[j], Bb1 + (wn * 32 + j * 16) * 40 + ks * 16, 40);
            }
#pragma unroll
            for (int i = 0; i < 2; i++)
#pragma unroll
                for (int j = 0; j < 2; j++) {
                    wmma::mma_sync(acc[i][j], ah[i], bh[j], acc[i][j]);
                    wmma::mma_sync(acc[i][j], ah[i], bl[j], acc[i][j]);
                    wmma::mma_sync(acc[i][j], al[i], bh[j], acc[i][j]);
                }
        }
        __syncthreads();
    }

#pragma unroll
    for (int i = 0; i < 2; i++)
#pragma unroll
        for (int j = 0; j < 2; j++) {
            float* cp = g_pi + ((size_t)d * (NB * NT) + mBase + wm * 32 + i * 16) * NG
                             + nBase + wn * 32 + j * 16;
            wmma::store_matrix_sync(cp, acc[i][j], NG, wmma::mem_row_major);
        }
}

// ---------------- FUSED step: gates (fp16 Ws, MLP-preserving) + proj partial ---
// Identical loop/index structure to the R4/R15 fp32 core: 16 independent weight
// loads per lane per sweep; only the load width shrinks 16B -> 8B.
__global__ void __launch_bounds__(256, 4)
step_fused_kernel(const float* __restrict__ bs_l,
                  const int*   __restrict__ mask, int t)
{
    pdl_sync();
    __shared__ float sh[NB * NH];
    __shared__ float s_sm[8][4];
    const int d  = blockIdx.x >> 9;
    const int cb = (blockIdx.x & 511) * 8;
    const int td = d ? (NT - 1 - t) : t;
    const int tid = threadIdx.x;

    const float* hsrc = g_h + (size_t)d * NB * NH;
    for (int i = tid; i < NB * NH; i += 256) sh[i] = hsrc[i];
    __syncthreads();

    const int w = tid >> 5, lane = tid & 31;
    const int j = cb + w;
    const __half* wbase = g_wsh + (size_t)d * NG * ND;

    float acc[4][4];
#pragma unroll
    for (int q = 0; q < 4; q++)
#pragma unroll
        for (int b = 0; b < 4; b++) acc[q][b] = 0.0f;

#pragma unroll
    for (int it = 0; it < 4; it++) {
        const int k = it * 128 + lane * 4;
        float4 hv0 = *(const float4*)&sh[0 * NH + k];
        float4 hv1 = *(const float4*)&sh[1 * NH + k];
        float4 hv2 = *(const float4*)&sh[2 * NH + k];
        float4 hv3 = *(const float4*)&sh[3 * NH + k];
#pragma unroll
        for (int q = 0; q < 4; q++) {
            uint2 wu = *(const uint2*)&wbase[(size_t)(q * NC + j) * ND + k];
            float4 wv = h4tof4(wu);
            acc[q][0] += dot4(wv, hv0);
            acc[q][1] += dot4(wv, hv1);
            acc[q][2] += dot4(wv, hv2);
            acc[q][3] += dot4(wv, hv3);
        }
    }
#pragma unroll
    for (int off = 16; off > 0; off >>= 1)
#pragma unroll
        for (int q = 0; q < 4; q++)
#pragma unroll
            for (int b = 0; b < 4; b++)
                acc[q][b] += __shfl_xor_sync(0xffffffffu, acc[q][b], off);

    if (lane < 4) {
        const int b = lane;
        const float* pib = g_pi + (((size_t)d * NB + b) * NT + td) * NG;
        const float* bsd = bs_l + (size_t)d * NG;
        float gi = acc[0][b] + __ldcs(&pib[0 * NC + j]) + bsd[0 * NC + j];
        float gf = acc[1][b] + __ldcs(&pib[1 * NC + j]) + bsd[1 * NC + j];
        float gg = acc[2][b] + __ldcs(&pib[2 * NC + j]) + bsd[2 * NC + j];
        float go = acc[3][b] + __ldcs(&pib[3 * NC + j]) + bsd[3 * NC + j];

        const size_t ci = ((size_t)d * NB + b) * NC + j;
        float cold = g_c[ci];
        float cn = clip3(sigmoidf_(gi) * tanhf(gg) + sigmoidf_(gf) * cold);
        if (mask[b * NT + td] != 0) g_c[ci] = cn;
        s_sm[w][b] = sigmoidf_(go) * tanhf(cn);
    }
    __syncthreads();

    // ---- proj partial: outputs i0 = tid, i1 = tid + 256 ----
    const float* wpT = g_wpT + (size_t)d * NC * NH + (size_t)cb * NH;
    float pa0[4] = {0.f, 0.f, 0.f, 0.f};
    float pa1[4] = {0.f, 0.f, 0.f, 0.f};
#pragma unroll
    for (int jl = 0; jl < 8; jl++) {
        float w0 = wpT[(size_t)jl * NH + tid];
        float w1 = wpT[(size_t)jl * NH + tid + 256];
#pragma unroll
        for (int b = 0; b < 4; b++) {
            pa0[b] += w0 * s_sm[jl][b];
            pa1[b] += w1 * s_sm[jl][b];
        }
    }
    const int part = (blockIdx.x & 511) >> 4;   // 0..31
    float* dst = g_hpp[t & 1][part] + (size_t)d * NB * NH;
#pragma unroll
    for (int b = 0; b < 4; b++) {
        atomicAdd(&dst[b * NH + tid],       pa0[b]);
        atomicAdd(&dst[b * NH + tid + 256], pa1[b]);
    }
}

// ---------------- hfin: sum partials -> h, y; re-zero --------------------------
__global__ void __launch_bounds__(256)
hfin_kernel(const int* __restrict__ mask, int t)
{
    pdl_sync();
    const int idx = blockIdx.x * 256 + threadIdx.x;   // 0..4095
    const int d = idx >> 11;
    const int b = (idx >> 9) & 3;
    const int i = idx & 511;
    const int td = d ? (NT - 1 - t) : t;
    const int par = t & 1;

    float v = 0.0f;
#pragma unroll
    for (int k = 0; k < NPART; k++) {
        v += g_hpp[par][k][idx];
        g_hpp[par][k][idx] = 0.0f;    // ready for step t+2
    }
    v = clip3(v);
    const size_t yi = (((size_t)d * NB + b) * NT + td) * NH + i;
    if (mask[b * NT + td] != 0) {
        g_h[idx] = v;
        g_y[yi] = v;
    } else {
        g_y[yi] = 0.0f;
    }
}

// ---------------- finalize layer: skip-add, write output, feed next layer ------
__global__ void __launch_bounds__(512)
finalize_kernel(float* __restrict__ out, int l)
{
    pdl_sync();
    const int idx = blockIdx.x * blockDim.x + threadIdx.x;
    const int i  = idx & (NH - 1);
    const int tt = (idx >> 9) & (NT - 1);
    const int b  = (idx >> 15) & (NB - 1);
    const int d  = idx >> 17;
    float z = g_y[idx] + (l ? g_x[idx] : 0.0f);
    g_x[idx] = z;
    out[(((size_t)l * NB + b) * NT + tt) * (2 * NH) + d * NH + i] = z;
}

// ---------------- PDL launch helper ----------------
template <typename F, typename... Args>
static inline void launch_pdl(F kern, dim3 grid, dim3 block, size_t smem, Args... args)
{
    cudaLaunchConfig_t cfg = {};
    cfg.gridDim = grid;
    cfg.blockDim = block;
    cfg.dynamicSmemBytes = smem;
    cfg.stream = 0;
    cudaLaunchAttribute attr[1];
    attr[0].id = cudaLaunchAttributeProgrammaticStreamSerialization;
    attr[0].val.programmaticStreamSerializationAllowed = 1;
    cfg.attrs = attr;
    cfg.numAttrs = 1;
    cudaLaunchKernelEx(&cfg, kern, args...);
}

// ---------------- launcher ----------------
extern "C" void kernel_launch(void* const* d_in, const int* in_sizes, int n_in,
                              void* d_out, int out_size)
{
    const float* inputs = (const float*)d_in[0];   // (4,64,512)
    const int*   mask   = (const int*)  d_in[1];   // (4,64)
    const float* Wi     = (const float*)d_in[2];   // (2,2,16384,512)
    const float* Ws     = (const float*)d_in[3];   // (2,2,16384,512)
    const float* bs     = (const float*)d_in[4];   // (2,2,16384)
    const float* Wp     = (const float*)d_in[5];   // (2,2,512,4096)
    float* out = (float*)d_out;                    // (2,4,64,1024)

    cudaFuncSetAttribute(pi3_kernel,
                         cudaFuncAttributeMaxDynamicSharedMemorySize,
                         PI_SMEM_BYTES);

    const int wiBlocks = (int)(WI_ELEMS / 8 / 256);  // 8192
    const int wsBlocks = (int)(WS_ELEMS / 8 / 256);  // 8192
    const int aBlocks  = (int)(A_ELEMS / 8 / 256);   // 128

    for (int l = 0; l < NL; l++) {
        const float* Wi_l = Wi + (size_t)l * 2 * NG * ND;
        const float* Ws_l = Ws + (size_t)l * 2 * NG * ND;
        const float* bs_l = bs + (size_t)l * 2 * NG;
        const float* Wp_l = Wp + (size_t)l * 2 * NH * NC;

        launch_pdl(init_state_kernel, dim3(144), dim3(256), 0);
        launch_pdl(convert_wi_kernel, dim3(wiBlocks), dim3(256), 0, Wi_l);
        launch_pdl(convert_ws_kernel, dim3(wsBlocks), dim3(256), 0, Ws_l);
        launch_pdl(convert_a_kernel, dim3(aBlocks), dim3(256), 0, inputs, l);
        launch_pdl(transpose_wp_kernel, dim3(128, 16, 2), dim3(256), 0, Wp_l);

        dim3 gp(NG / 64, (NB * NT) / 128, 2);
        launch_pdl(pi3_kernel, gp, dim3(256), (size_t)PI_SMEM_BYTES);

        for (int t = 0; t < NT; t++) {
            launch_pdl(step_fused_kernel, dim3(1024), dim3(256), 0, bs_l, mask, t);
            launch_pdl(hfin_kernel, dim3(16), dim3(256), 0, mask, t);
        }
        launch_pdl(finalize_kernel, dim3(512), dim3(512), 0, out, l);
    }
}